// round 8
// baseline (speedup 1.0000x reference)
#include <cuda_runtime.h>
#include <cuda_bf16.h>
#include <cuda_fp16.h>
#include <cstdint>

// Problem constants
#define BB    2
#define HW    4096
#define NTGT  4096
#define CC    512
#define HH    8
#define KNN   32
#define DH    64
#define MROWS (BB * HW)      // 8192
#define SCALE 0.125f

// ---------------- scratch (device globals: allocation-free) ----------------
__device__ float  g_q[(size_t)MROWS * CC];
__device__ __half g_kh[(size_t)MROWS * CC];
__device__ __half g_vh[(size_t)MROWS * CC];
__device__ __nv_bfloat16 g_Shi[(size_t)MROWS * CC];
__device__ __nv_bfloat16 g_Slo[(size_t)MROWS * CC];
__device__ __nv_bfloat16 g_Thi[(size_t)MROWS * CC];
__device__ __nv_bfloat16 g_Tlo[(size_t)MROWS * CC];
__device__ __nv_bfloat16 g_Ohi[(size_t)MROWS * CC];
__device__ __nv_bfloat16 g_Olo[(size_t)MROWS * CC];
__device__ __nv_bfloat16 g_Wt_hi[4][CC * CC];        // [N][K]
__device__ __nv_bfloat16 g_Wt_lo[4][CC * CC];

// ---------------- helpers ----------------------------------------------------
__device__ __forceinline__ uint32_t smem_to_u32(const void* p) {
    uint32_t a;
    asm("{ .reg .u64 t; cvta.to.shared.u64 t, %1; cvt.u32.u64 %0, t; }"
        : "=r"(a) : "l"(p));
    return a;
}
__device__ __forceinline__ void cp16(uint32_t dst, const void* src) {
    asm volatile("cp.async.cg.shared.global [%0], [%1], 16;" :: "r"(dst), "l"(src));
}
#define CP_COMMIT() asm volatile("cp.async.commit_group;" ::: "memory")
#define CP_WAIT(n)  asm volatile("cp.async.wait_group %0;" :: "n"(n) : "memory")

__device__ __forceinline__ uint32_t pack2(__nv_bfloat16 a, __nv_bfloat16 b) {
    __nv_bfloat162 t; t.x = a; t.y = b;
    return *reinterpret_cast<uint32_t*>(&t);
}

#define MMA_BF16(d, a0, a1, a2, a3, b0, b1) \
    asm volatile( \
        "mma.sync.aligned.m16n8k16.row.col.f32.bf16.bf16.f32 " \
        "{%0,%1,%2,%3}, {%4,%5,%6,%7}, {%8,%9}, {%0,%1,%2,%3};" \
        : "+f"((d)[0]), "+f"((d)[1]), "+f"((d)[2]), "+f"((d)[3]) \
        : "r"(a0), "r"(a1), "r"(a2), "r"(a3), "r"(b0), "r"(b1))

// ---------------- fused weight transpose + split (all 4 weights) ------------
__global__ void transpose_split_all(const float* __restrict__ W0,
                                    const float* __restrict__ W1,
                                    const float* __restrict__ W2,
                                    const float* __restrict__ W3,
                                    __nv_bfloat16* __restrict__ hi,
                                    __nv_bfloat16* __restrict__ lo)
{
    __shared__ float t[32][33];
    const int w  = blockIdx.z;
    const float* W = (w == 0) ? W0 : (w == 1) ? W1 : (w == 2) ? W2 : W3;
    const size_t wo = (size_t)w * CC * CC;
    const int kt = blockIdx.x * 32;
    const int nt = blockIdx.y * 32;
    const int tx = threadIdx.x, ty = threadIdx.y;
    #pragma unroll
    for (int i = 0; i < 4; ++i)
        t[ty + i * 8][tx] = W[(size_t)(kt + ty + i * 8) * CC + nt + tx];
    __syncthreads();
    #pragma unroll
    for (int i = 0; i < 4; ++i) {
        float x = t[tx][ty + i * 8];
        __nv_bfloat16 h = __float2bfloat16_rn(x);
        __nv_bfloat16 l = __float2bfloat16_rn(x - __bfloat162float(h));
        size_t o = wo + (size_t)(nt + ty + i * 8) * CC + kt + tx;
        hi[o] = h;
        lo[o] = l;
    }
}

// ---------------- fused activation split: src + tgt -------------------------
__global__ void __launch_bounds__(256) split2_kernel(
    const float* __restrict__ S, const float* __restrict__ T,
    __nv_bfloat16* __restrict__ shi, __nv_bfloat16* __restrict__ slo,
    __nv_bfloat16* __restrict__ thi, __nv_bfloat16* __restrict__ tlo)
{
    const int half = gridDim.x >> 1;
    const bool is_t = blockIdx.x >= half;
    const float* X = is_t ? T : S;
    __nv_bfloat16* hi = is_t ? thi : shi;
    __nv_bfloat16* lo = is_t ? tlo : slo;
    const int i = (is_t ? blockIdx.x - half : blockIdx.x) * 256 + threadIdx.x;
    const float4 x = reinterpret_cast<const float4*>(X)[i];
    __nv_bfloat16 h0 = __float2bfloat16_rn(x.x);
    __nv_bfloat16 h1 = __float2bfloat16_rn(x.y);
    __nv_bfloat16 h2 = __float2bfloat16_rn(x.z);
    __nv_bfloat16 h3 = __float2bfloat16_rn(x.w);
    __nv_bfloat16 l0 = __float2bfloat16_rn(x.x - __bfloat162float(h0));
    __nv_bfloat16 l1 = __float2bfloat16_rn(x.y - __bfloat162float(h1));
    __nv_bfloat16 l2 = __float2bfloat16_rn(x.z - __bfloat162float(h2));
    __nv_bfloat16 l3 = __float2bfloat16_rn(x.w - __bfloat162float(h3));
    reinterpret_cast<uint2*>(hi)[i] = make_uint2(pack2(h0, h1), pack2(h2, h3));
    reinterpret_cast<uint2*>(lo)[i] = make_uint2(pack2(l0, l1), pack2(l2, l3));
}

// ---------------- bf16 mma.sync GEMM v3: term-major ordering ---------------
#define ROWB 80
#define A_STG (128 * ROWB)          // 10240
#define B_STG (256 * ROWB)          // 20480
#define OFF_AHI 0
#define OFF_ALO (3 * A_STG)
#define OFF_BHI (6 * A_STG)
#define OFF_BLO (OFF_BHI + 3 * B_STG)
#define SM_TOT  (OFF_BLO + 3 * B_STG)   // 184320

template <typename OutT>
__device__ __forceinline__ void store2(OutT* p, float a, float b);
template <> __device__ __forceinline__ void store2<float>(float* p, float a, float b) {
    *reinterpret_cast<float2*>(p) = make_float2(a, b);
}
template <> __device__ __forceinline__ void store2<__half>(__half* p, float a, float b) {
    *reinterpret_cast<__half2*>(p) = __floats2half2_rn(a, b);
}

template <typename OutT>
__global__ void __launch_bounds__(512, 1) mma_gemm_bias(
    const __nv_bfloat16* __restrict__ Ahi, const __nv_bfloat16* __restrict__ Alo,
    const __nv_bfloat16* __restrict__ Whi, const __nv_bfloat16* __restrict__ Wlo,
    const float* __restrict__ bias, OutT* __restrict__ C)
{
    extern __shared__ char sm[];
    const uint32_t sb = smem_to_u32(sm);
    const int tid  = threadIdx.x;
    const int wid  = tid >> 5;
    const int lane = tid & 31;
    const int bm   = blockIdx.y * 128;
    const int bn   = blockIdx.x * 256;
    const int wm   = wid & 1;
    const int wn   = wid >> 1;

    const int ar = tid >> 2;
    const int aq = tid & 3;

    float acc[4][4][4];
    #pragma unroll
    for (int a = 0; a < 4; ++a)
        #pragma unroll
        for (int b = 0; b < 4; ++b)
            #pragma unroll
            for (int c = 0; c < 4; ++c) acc[a][b][c] = 0.f;

    auto load_stage = [&](int s, int kt) {
        const int kb = kt * 32;
        {
            const uint32_t so = (uint32_t)(ar * ROWB + aq * 16 + s * A_STG);
            const size_t  ga = (size_t)(bm + ar) * CC + kb + aq * 8;
            cp16(sb + OFF_AHI + so, Ahi + ga);
            cp16(sb + OFF_ALO + so, Alo + ga);
        }
        #pragma unroll
        for (int c = 0; c < 2; ++c) {
            const int row = c * 128 + ar;
            const uint32_t so = (uint32_t)(row * ROWB + aq * 16 + s * B_STG);
            const size_t  gb = (size_t)(bn + row) * CC + kb + aq * 8;
            cp16(sb + OFF_BHI + so, Whi + gb);
            cp16(sb + OFF_BLO + so, Wlo + gb);
        }
    };

    load_stage(0, 0);
    CP_COMMIT();
    load_stage(1, 1);
    CP_COMMIT();

    const int sub16 = lane & 15;
    const int ahalf = lane >> 4;
    const int bn8   = lane & 7;
    const int bk16  = (lane >> 3) & 1;

    #pragma unroll 1
    for (int kt = 0; kt < 16; ++kt) {
        const int s = kt % 3;
        if (kt >= 14) { CP_WAIT(0); } else { CP_WAIT(1); }
        __syncthreads();
        if (kt + 2 < 16) {
            load_stage((kt + 2) % 3, kt + 2);
            CP_COMMIT();
        }

        const uint32_t aBase = sb + (uint32_t)(s * A_STG);
        const uint32_t bBase = sb + (uint32_t)(s * B_STG);

        #pragma unroll
        for (int s2 = 0; s2 < 2; ++s2) {
            const int kbyte = s2 * 32;

            // ---- load ALL fragments for this k-step first ----
            uint32_t bh[4][2], bl[4][2];
            #pragma unroll
            for (int nf = 0; nf < 4; ++nf) {
                const uint32_t brow = (uint32_t)(wn * 32 + nf * 8 + bn8);
                const uint32_t ba = bBase + brow * ROWB + kbyte + bk16 * 16;
                asm volatile(
                    "ldmatrix.sync.aligned.m8n8.x2.shared.b16 {%0,%1}, [%2];"
                    : "=r"(bh[nf][0]), "=r"(bh[nf][1]) : "r"(ba + OFF_BHI));
                asm volatile(
                    "ldmatrix.sync.aligned.m8n8.x2.shared.b16 {%0,%1}, [%2];"
                    : "=r"(bl[nf][0]), "=r"(bl[nf][1]) : "r"(ba + OFF_BLO));
            }
            uint32_t ah[4][4], al[4][4];
            #pragma unroll
            for (int mf = 0; mf < 4; ++mf) {
                const uint32_t arow = (uint32_t)(wm * 64 + mf * 16 + sub16);
                const uint32_t aa = aBase + arow * ROWB + kbyte + ahalf * 16;
                asm volatile(
                    "ldmatrix.sync.aligned.m8n8.x4.shared.b16 {%0,%1,%2,%3}, [%4];"
                    : "=r"(ah[mf][0]), "=r"(ah[mf][1]), "=r"(ah[mf][2]), "=r"(ah[mf][3])
                    : "r"(aa + OFF_AHI));
                asm volatile(
                    "ldmatrix.sync.aligned.m8n8.x4.shared.b16 {%0,%1,%2,%3}, [%4];"
                    : "=r"(al[mf][0]), "=r"(al[mf][1]), "=r"(al[mf][2]), "=r"(al[mf][3])
                    : "r"(aa + OFF_ALO));
            }

            // ---- term-major mma: same-acc reuse distance = 16 ----
            #pragma unroll
            for (int mf = 0; mf < 4; ++mf)
                #pragma unroll
                for (int nf = 0; nf < 4; ++nf)
                    MMA_BF16(acc[mf][nf], ah[mf][0], ah[mf][1], ah[mf][2], ah[mf][3],
                             bh[nf][0], bh[nf][1]);
            #pragma unroll
            for (int mf = 0; mf < 4; ++mf)
                #pragma unroll
                for (int nf = 0; nf < 4; ++nf)
                    MMA_BF16(acc[mf][nf], ah[mf][0], ah[mf][1], ah[mf][2], ah[mf][3],
                             bl[nf][0], bl[nf][1]);
            #pragma unroll
            for (int mf = 0; mf < 4; ++mf)
                #pragma unroll
                for (int nf = 0; nf < 4; ++nf)
                    MMA_BF16(acc[mf][nf], al[mf][0], al[mf][1], al[mf][2], al[mf][3],
                             bh[nf][0], bh[nf][1]);
        }
    }

    const int g = lane >> 2;
    const int t = lane & 3;
    #pragma unroll
    for (int mf = 0; mf < 4; ++mf) {
        const int row = bm + wm * 64 + mf * 16 + g;
        #pragma unroll
        for (int nf = 0; nf < 4; ++nf) {
            const int col = bn + wn * 32 + nf * 8 + 2 * t;
            const float b0 = __ldg(bias + col);
            const float b1 = __ldg(bias + col + 1);
            float* d = acc[mf][nf];
            store2<OutT>(C + (size_t)row * CC + col, d[0] + b0, d[1] + b1);
            store2<OutT>(C + (size_t)(row + 8) * CC + col, d[2] + b0, d[3] + b1);
        }
    }
}

// ---------------- gather attention: fp16 K/V, one warp per (b,q) ------------
__global__ void __launch_bounds__(256) attn_kernel(
    const float* __restrict__ q, const __half* __restrict__ k,
    const __half* __restrict__ v, const int* __restrict__ indices,
    const float* __restrict__ weights,
    __nv_bfloat16* __restrict__ ohi, __nv_bfloat16* __restrict__ olo)
{
    __shared__ float slog[8 * 8 * 33];
    const int wid  = threadIdx.x >> 5;
    const int lane = threadIdx.x & 31;
    const int bq   = blockIdx.x * 8 + wid;
    const int b    = bq >> 12;
    float* sl = slog + wid * (8 * 33);

    const __half* kb = k + (size_t)b * NTGT * CC;
    const __half* vb = v + (size_t)b * NTGT * CC;

    const int idxl = indices[(size_t)bq * KNN + lane];

    float qf[2][8];
    {
        const float4* qrow = reinterpret_cast<const float4*>(q + (size_t)bq * CC);
        #pragma unroll
        for (int i = 0; i < 2; ++i) {
            float4 a = qrow[i * 64 + lane * 2];
            float4 c = qrow[i * 64 + lane * 2 + 1];
            qf[i][0] = a.x; qf[i][1] = a.y; qf[i][2] = a.z; qf[i][3] = a.w;
            qf[i][4] = c.x; qf[i][5] = c.y; qf[i][6] = c.z; qf[i][7] = c.w;
        }
    }

    #pragma unroll 4
    for (int j = 0; j < KNN; ++j) {
        const int ij = __shfl_sync(0xffffffffu, idxl, j);
        const uint4* krow = reinterpret_cast<const uint4*>(kb + (size_t)ij * CC);
        float part[2];
        #pragma unroll
        for (int i = 0; i < 2; ++i) {
            const uint4 kk = krow[i * 32 + lane];
            const __half2* kh = reinterpret_cast<const __half2*>(&kk);
            float p = 0.f;
            #pragma unroll
            for (int h2 = 0; h2 < 4; ++h2) {
                const float2 kf = __half22float2(kh[h2]);
                p = fmaf(qf[i][2 * h2], kf.x, p);
                p = fmaf(qf[i][2 * h2 + 1], kf.y, p);
            }
            part[i] = p;
        }
        #pragma unroll
        for (int off = 4; off >= 1; off >>= 1) {
            part[0] += __shfl_xor_sync(0xffffffffu, part[0], off);
            part[1] += __shfl_xor_sync(0xffffffffu, part[1], off);
        }
        if ((lane & 7) == 0) {
            sl[(0 * 4 + (lane >> 3)) * 33 + j] = part[0];
            sl[(1 * 4 + (lane >> 3)) * 33 + j] = part[1];
        }
    }
    __syncwarp();

    {
        const int h  = lane >> 2;
        const int j0 = lane & 3;
        float vals[8];
        #pragma unroll
        for (int t = 0; t < 8; ++t) {
            const int j = j0 + 4 * t;
            vals[t] = sl[h * 33 + j] * SCALE + weights[(size_t)bq * KNN + j];
        }
        float m = vals[0];
        #pragma unroll
        for (int t = 1; t < 8; ++t) m = fmaxf(m, vals[t]);
        m = fmaxf(m, __shfl_xor_sync(0xffffffffu, m, 1));
        m = fmaxf(m, __shfl_xor_sync(0xffffffffu, m, 2));
        float s = 0.f;
        #pragma unroll
        for (int t = 0; t < 8; ++t) { vals[t] = __expf(vals[t] - m); s += vals[t]; }
        s += __shfl_xor_sync(0xffffffffu, s, 1);
        s += __shfl_xor_sync(0xffffffffu, s, 2);
        const float inv = 1.f / s;
        #pragma unroll
        for (int t = 0; t < 8; ++t) sl[h * 33 + j0 + 4 * t] = vals[t] * inv;
    }
    __syncwarp();

    float acc[2][8];
    #pragma unroll
    for (int i = 0; i < 2; ++i)
        #pragma unroll
        for (int d = 0; d < 8; ++d) acc[i][d] = 0.f;

    const int hsub = lane >> 3;
    #pragma unroll 4
    for (int j = 0; j < KNN; ++j) {
        const int ij = __shfl_sync(0xffffffffu, idxl, j);
        const uint4* vrow = reinterpret_cast<const uint4*>(vb + (size_t)ij * CC);
        #pragma unroll
        for (int i = 0; i < 2; ++i) {
            const float pj = sl[(i * 4 + hsub) * 33 + j];
            const uint4 vv = vrow[i * 32 + lane];
            const __half2* vh = reinterpret_cast<const __half2*>(&vv);
            #pragma unroll
            for (int h2 = 0; h2 < 4; ++h2) {
                const float2 vf = __half22float2(vh[h2]);
                acc[i][2 * h2]     = fmaf(pj, vf.x, acc[i][2 * h2]);
                acc[i][2 * h2 + 1] = fmaf(pj, vf.y, acc[i][2 * h2 + 1]);
            }
        }
    }

    #pragma unroll
    for (int i = 0; i < 2; ++i) {
        const size_t d = (size_t)bq * CC + i * 256 + lane * 8;
        uint32_t hw[4], lw[4];
        #pragma unroll
        for (int p = 0; p < 4; ++p) {
            float x0 = acc[i][2 * p], x1 = acc[i][2 * p + 1];
            __nv_bfloat16 h0 = __float2bfloat16_rn(x0);
            __nv_bfloat16 h1 = __float2bfloat16_rn(x1);
            __nv_bfloat16 l0 = __float2bfloat16_rn(x0 - __bfloat162float(h0));
            __nv_bfloat16 l1 = __float2bfloat16_rn(x1 - __bfloat162float(h1));
            hw[p] = pack2(h0, h1);
            lw[p] = pack2(l0, l1);
        }
        *reinterpret_cast<uint4*>(ohi + d) = make_uint4(hw[0], hw[1], hw[2], hw[3]);
        *reinterpret_cast<uint4*>(olo + d) = make_uint4(lw[0], lw[1], lw[2], lw[3]);
    }
}

// ---------------- launch ----------------------------------------------------
extern "C" void kernel_launch(void* const* d_in, const int* in_sizes, int n_in,
                              void* d_out, int out_size)
{
    const float* src = (const float*)d_in[0];
    const float* tgt = (const float*)d_in[1];
    const int*   idx = (const int*)d_in[2];
    const float* wts = (const float*)d_in[3];
    const float* Wq  = (const float*)d_in[4];
    const float* bq  = (const float*)d_in[5];
    const float* Wk  = (const float*)d_in[6];
    const float* bk  = (const float*)d_in[7];
    const float* Wv  = (const float*)d_in[8];
    const float* bv  = (const float*)d_in[9];
    const float* Wo  = (const float*)d_in[10];
    const float* bo  = (const float*)d_in[11];
    float*       out = (float*)d_out;

    void *pq, *pkh, *pvh, *pshi, *pslo, *pthi, *ptlo, *pohi, *polo, *pwhi, *pwlo;
    cudaGetSymbolAddress(&pq, g_q);
    cudaGetSymbolAddress(&pkh, g_kh);
    cudaGetSymbolAddress(&pvh, g_vh);
    cudaGetSymbolAddress(&pshi, g_Shi);
    cudaGetSymbolAddress(&pslo, g_Slo);
    cudaGetSymbolAddress(&pthi, g_Thi);
    cudaGetSymbolAddress(&ptlo, g_Tlo);
    cudaGetSymbolAddress(&pohi, g_Ohi);
    cudaGetSymbolAddress(&polo, g_Olo);
    cudaGetSymbolAddress(&pwhi, g_Wt_hi);
    cudaGetSymbolAddress(&pwlo, g_Wt_lo);
    float*  gq  = (float*)pq;
    __half* gkh = (__half*)pkh;
    __half* gvh = (__half*)pvh;
    __nv_bfloat16* shi = (__nv_bfloat16*)pshi;
    __nv_bfloat16* slo = (__nv_bfloat16*)pslo;
    __nv_bfloat16* thi = (__nv_bfloat16*)pthi;
    __nv_bfloat16* tlo = (__nv_bfloat16*)ptlo;
    __nv_bfloat16* ohi = (__nv_bfloat16*)pohi;
    __nv_bfloat16* olo = (__nv_bfloat16*)polo;
    __nv_bfloat16* whi = (__nv_bfloat16*)pwhi;
    __nv_bfloat16* wlo = (__nv_bfloat16*)pwlo;

    static bool attr_set = false;
    if (!attr_set) {
        cudaFuncSetAttribute(mma_gemm_bias<float>,
                             cudaFuncAttributeMaxDynamicSharedMemorySize, SM_TOT);
        cudaFuncSetAttribute(mma_gemm_bias<__half>,
                             cudaFuncAttributeMaxDynamicSharedMemorySize, SM_TOT);
        attr_set = true;
    }

    const size_t WS = (size_t)CC * CC;

    dim3 tgrid(CC / 32, CC / 32, 4), tblk(32, 8);
    transpose_split_all<<<tgrid, tblk>>>(Wq, Wk, Wv, Wo, whi, wlo);

    const int nsplit = MROWS * CC / 4 / 256;
    split2_kernel<<<2 * nsplit, 256>>>(src, tgt, shi, slo, thi, tlo);

    dim3 ggrid(CC / 256, MROWS / 128);   // (2, 64) = 128 CTAs
    mma_gemm_bias<float><<<ggrid, 512, SM_TOT>>>(shi, slo, whi + 0 * WS, wlo + 0 * WS, bq, gq);
    mma_gemm_bias<__half><<<ggrid, 512, SM_TOT>>>(thi, tlo, whi + 1 * WS, wlo + 1 * WS, bk, gkh);
    mma_gemm_bias<__half><<<ggrid, 512, SM_TOT>>>(thi, tlo, whi + 2 * WS, wlo + 2 * WS, bv, gvh);

    attn_kernel<<<BB * HW / 8, 256>>>(gq, gkh, gvh, idx, wts, ohi, olo);

    mma_gemm_bias<float><<<ggrid, 512, SM_TOT>>>(ohi, olo, whi + 3 * WS, wlo + 3 * WS, bo, out);
}

// round 9
// speedup vs baseline: 1.2527x; 1.2527x over previous
#include <cuda_runtime.h>
#include <cuda_bf16.h>
#include <cuda_fp16.h>
#include <cstdint>

// Problem constants
#define BB    2
#define HW    4096
#define NTGT  4096
#define CC    512
#define HH    8
#define KNN   32
#define DH    64
#define MROWS (BB * HW)      // 8192
#define SCALE 0.125f

// ---------------- scratch (device globals: allocation-free) ----------------
__device__ float  g_q[(size_t)MROWS * CC];
__device__ __half g_kh[(size_t)MROWS * CC];
__device__ __half g_vh[(size_t)MROWS * CC];
__device__ __half g_Shi[(size_t)MROWS * CC];   // src fp16 hi/lo
__device__ __half g_Slo[(size_t)MROWS * CC];
__device__ __half g_Thi[(size_t)MROWS * CC];   // tgt fp16 hi/lo
__device__ __half g_Tlo[(size_t)MROWS * CC];
__device__ __half g_Ohi[(size_t)MROWS * CC];   // attn-out fp16 hi/lo
__device__ __half g_Olo[(size_t)MROWS * CC];
__device__ __half g_Wt[4][CC * CC];            // [N][K] fp16 single

// ---------------- helpers ----------------------------------------------------
__device__ __forceinline__ uint32_t smem_to_u32(const void* p) {
    uint32_t a;
    asm("{ .reg .u64 t; cvta.to.shared.u64 t, %1; cvt.u32.u64 %0, t; }"
        : "=r"(a) : "l"(p));
    return a;
}
__device__ __forceinline__ void cp16(uint32_t dst, const void* src) {
    asm volatile("cp.async.cg.shared.global [%0], [%1], 16;" :: "r"(dst), "l"(src));
}
#define CP_COMMIT() asm volatile("cp.async.commit_group;" ::: "memory")
#define CP_WAIT(n)  asm volatile("cp.async.wait_group %0;" :: "n"(n) : "memory")

__device__ __forceinline__ uint32_t pack2h(__half a, __half b) {
    __half2 t = __halves2half2(a, b);
    return *reinterpret_cast<uint32_t*>(&t);
}

#define MMA_F16(d, a0, a1, a2, a3, b0, b1) \
    asm volatile( \
        "mma.sync.aligned.m16n8k16.row.col.f32.f16.f16.f32 " \
        "{%0,%1,%2,%3}, {%4,%5,%6,%7}, {%8,%9}, {%0,%1,%2,%3};" \
        : "+f"((d)[0]), "+f"((d)[1]), "+f"((d)[2]), "+f"((d)[3]) \
        : "r"(a0), "r"(a1), "r"(a2), "r"(a3), "r"(b0), "r"(b1))

// ---------------- fused weight transpose -> fp16 [N][K] ---------------------
__global__ void transpose_half_all(const float* __restrict__ W0,
                                   const float* __restrict__ W1,
                                   const float* __restrict__ W2,
                                   const float* __restrict__ W3,
                                   __half* __restrict__ out)
{
    __shared__ float t[32][33];
    const int w  = blockIdx.z;
    const float* W = (w == 0) ? W0 : (w == 1) ? W1 : (w == 2) ? W2 : W3;
    const size_t wo = (size_t)w * CC * CC;
    const int kt = blockIdx.x * 32;
    const int nt = blockIdx.y * 32;
    const int tx = threadIdx.x, ty = threadIdx.y;
    #pragma unroll
    for (int i = 0; i < 4; ++i)
        t[ty + i * 8][tx] = W[(size_t)(kt + ty + i * 8) * CC + nt + tx];
    __syncthreads();
    #pragma unroll
    for (int i = 0; i < 4; ++i) {
        float x = t[tx][ty + i * 8];
        out[wo + (size_t)(nt + ty + i * 8) * CC + kt + tx] = __float2half_rn(x);
    }
}

// ---------------- fused activation split: src + tgt -> fp16 hi/lo ----------
__global__ void __launch_bounds__(256) split2_kernel(
    const float* __restrict__ S, const float* __restrict__ T,
    __half* __restrict__ shi, __half* __restrict__ slo,
    __half* __restrict__ thi, __half* __restrict__ tlo)
{
    const int half = gridDim.x >> 1;
    const bool is_t = blockIdx.x >= half;
    const float* X = is_t ? T : S;
    __half* hi = is_t ? thi : shi;
    __half* lo = is_t ? tlo : slo;
    const int i = (is_t ? blockIdx.x - half : blockIdx.x) * 256 + threadIdx.x;
    const float4 x = reinterpret_cast<const float4*>(X)[i];
    __half h0 = __float2half_rn(x.x);
    __half h1 = __float2half_rn(x.y);
    __half h2 = __float2half_rn(x.z);
    __half h3 = __float2half_rn(x.w);
    __half l0 = __float2half_rn(x.x - __half2float(h0));
    __half l1 = __float2half_rn(x.y - __half2float(h1));
    __half l2 = __float2half_rn(x.z - __half2float(h2));
    __half l3 = __float2half_rn(x.w - __half2float(h3));
    reinterpret_cast<uint2*>(hi)[i] = make_uint2(pack2h(h0, h1), pack2h(h2, h3));
    reinterpret_cast<uint2*>(lo)[i] = make_uint2(pack2h(l0, l1), pack2h(l2, l3));
}

// ---------------- fp16 2-term mma GEMM: C = (Ahi+Alo) @ Wt^T + bias ---------
#define ROWB 80
#define A_STG (128 * ROWB)          // 10240
#define B_STG (256 * ROWB)          // 20480
#define OFF_AHI 0
#define OFF_ALO (3 * A_STG)
#define OFF_B   (6 * A_STG)
#define SM_TOT  (OFF_B + 3 * B_STG)   // 122880

template <typename OutT>
__device__ __forceinline__ void store2(OutT* p, float a, float b);
template <> __device__ __forceinline__ void store2<float>(float* p, float a, float b) {
    *reinterpret_cast<float2*>(p) = make_float2(a, b);
}
template <> __device__ __forceinline__ void store2<__half>(__half* p, float a, float b) {
    *reinterpret_cast<__half2*>(p) = __floats2half2_rn(a, b);
}

template <typename OutT>
__global__ void __launch_bounds__(512, 1) mma_gemm_bias(
    const __half* __restrict__ Ahi, const __half* __restrict__ Alo,
    const __half* __restrict__ Wt,
    const float* __restrict__ bias, OutT* __restrict__ C)
{
    extern __shared__ char sm[];
    const uint32_t sb = smem_to_u32(sm);
    const int tid  = threadIdx.x;
    const int wid  = tid >> 5;
    const int lane = tid & 31;
    const int bm   = blockIdx.y * 128;
    const int bn   = blockIdx.x * 256;
    const int wm   = wid & 1;
    const int wn   = wid >> 1;

    const int ar = tid >> 2;
    const int aq = tid & 3;

    float acc[4][4][4];
    #pragma unroll
    for (int a = 0; a < 4; ++a)
        #pragma unroll
        for (int b = 0; b < 4; ++b)
            #pragma unroll
            for (int c = 0; c < 4; ++c) acc[a][b][c] = 0.f;

    auto load_stage = [&](int s, int kt) {
        const int kb = kt * 32;
        {
            const uint32_t so = (uint32_t)(ar * ROWB + aq * 16 + s * A_STG);
            const size_t  ga = (size_t)(bm + ar) * CC + kb + aq * 8;
            cp16(sb + OFF_AHI + so, Ahi + ga);
            cp16(sb + OFF_ALO + so, Alo + ga);
        }
        #pragma unroll
        for (int c = 0; c < 2; ++c) {
            const int row = c * 128 + ar;
            const uint32_t so = (uint32_t)(row * ROWB + aq * 16 + s * B_STG);
            const size_t  gb = (size_t)(bn + row) * CC + kb + aq * 8;
            cp16(sb + OFF_B + so, Wt + gb);
        }
    };

    load_stage(0, 0);
    CP_COMMIT();
    load_stage(1, 1);
    CP_COMMIT();

    const int sub16 = lane & 15;
    const int ahalf = lane >> 4;
    const int bn8   = lane & 7;
    const int bk16  = (lane >> 3) & 1;

    #pragma unroll 1
    for (int kt = 0; kt < 16; ++kt) {
        const int s = kt % 3;
        if (kt >= 14) { CP_WAIT(0); } else { CP_WAIT(1); }
        __syncthreads();
        if (kt + 2 < 16) {
            load_stage((kt + 2) % 3, kt + 2);
            CP_COMMIT();
        }

        const uint32_t aBase = sb + (uint32_t)(s * A_STG);
        const uint32_t bBase = sb + (uint32_t)(s * B_STG);

        #pragma unroll
        for (int s2 = 0; s2 < 2; ++s2) {
            const int kbyte = s2 * 32;

            uint32_t bh[4][2];
            #pragma unroll
            for (int nf = 0; nf < 4; ++nf) {
                const uint32_t brow = (uint32_t)(wn * 32 + nf * 8 + bn8);
                const uint32_t ba = bBase + brow * ROWB + kbyte + bk16 * 16;
                asm volatile(
                    "ldmatrix.sync.aligned.m8n8.x2.shared.b16 {%0,%1}, [%2];"
                    : "=r"(bh[nf][0]), "=r"(bh[nf][1]) : "r"(ba + OFF_B));
            }
            uint32_t ah[4][4], al[4][4];
            #pragma unroll
            for (int mf = 0; mf < 4; ++mf) {
                const uint32_t arow = (uint32_t)(wm * 64 + mf * 16 + sub16);
                const uint32_t aa = aBase + arow * ROWB + kbyte + ahalf * 16;
                asm volatile(
                    "ldmatrix.sync.aligned.m8n8.x4.shared.b16 {%0,%1,%2,%3}, [%4];"
                    : "=r"(ah[mf][0]), "=r"(ah[mf][1]), "=r"(ah[mf][2]), "=r"(ah[mf][3])
                    : "r"(aa + OFF_AHI));
                asm volatile(
                    "ldmatrix.sync.aligned.m8n8.x4.shared.b16 {%0,%1,%2,%3}, [%4];"
                    : "=r"(al[mf][0]), "=r"(al[mf][1]), "=r"(al[mf][2]), "=r"(al[mf][3])
                    : "r"(aa + OFF_ALO));
            }

            #pragma unroll
            for (int mf = 0; mf < 4; ++mf)
                #pragma unroll
                for (int nf = 0; nf < 4; ++nf)
                    MMA_F16(acc[mf][nf], ah[mf][0], ah[mf][1], ah[mf][2], ah[mf][3],
                            bh[nf][0], bh[nf][1]);
            #pragma unroll
            for (int mf = 0; mf < 4; ++mf)
                #pragma unroll
                for (int nf = 0; nf < 4; ++nf)
                    MMA_F16(acc[mf][nf], al[mf][0], al[mf][1], al[mf][2], al[mf][3],
                            bh[nf][0], bh[nf][1]);
        }
    }

    const int g = lane >> 2;
    const int t = lane & 3;
    #pragma unroll
    for (int mf = 0; mf < 4; ++mf) {
        const int row = bm + wm * 64 + mf * 16 + g;
        #pragma unroll
        for (int nf = 0; nf < 4; ++nf) {
            const int col = bn + wn * 32 + nf * 8 + 2 * t;
            const float b0 = __ldg(bias + col);
            const float b1 = __ldg(bias + col + 1);
            float* d = acc[mf][nf];
            store2<OutT>(C + (size_t)row * CC + col, d[0] + b0, d[1] + b1);
            store2<OutT>(C + (size_t)(row + 8) * CC + col, d[2] + b0, d[3] + b1);
        }
    }
}

// ---------------- gather attention: fp16 K/V, one warp per (b,q) ------------
__global__ void __launch_bounds__(256) attn_kernel(
    const float* __restrict__ q, const __half* __restrict__ k,
    const __half* __restrict__ v, const int* __restrict__ indices,
    const float* __restrict__ weights,
    __half* __restrict__ ohi, __half* __restrict__ olo)
{
    __shared__ float slog[8 * 8 * 33];
    const int wid  = threadIdx.x >> 5;
    const int lane = threadIdx.x & 31;
    const int bq   = blockIdx.x * 8 + wid;
    const int b    = bq >> 12;
    float* sl = slog + wid * (8 * 33);

    const __half* kb = k + (size_t)b * NTGT * CC;
    const __half* vb = v + (size_t)b * NTGT * CC;

    const int idxl = indices[(size_t)bq * KNN + lane];

    float qf[2][8];
    {
        const float4* qrow = reinterpret_cast<const float4*>(q + (size_t)bq * CC);
        #pragma unroll
        for (int i = 0; i < 2; ++i) {
            float4 a = qrow[i * 64 + lane * 2];
            float4 c = qrow[i * 64 + lane * 2 + 1];
            qf[i][0] = a.x; qf[i][1] = a.y; qf[i][2] = a.z; qf[i][3] = a.w;
            qf[i][4] = c.x; qf[i][5] = c.y; qf[i][6] = c.z; qf[i][7] = c.w;
        }
    }

    #pragma unroll 4
    for (int j = 0; j < KNN; ++j) {
        const int ij = __shfl_sync(0xffffffffu, idxl, j);
        const uint4* krow = reinterpret_cast<const uint4*>(kb + (size_t)ij * CC);
        float part[2];
        #pragma unroll
        for (int i = 0; i < 2; ++i) {
            const uint4 kk = krow[i * 32 + lane];
            const __half2* kh = reinterpret_cast<const __half2*>(&kk);
            float p = 0.f;
            #pragma unroll
            for (int h2 = 0; h2 < 4; ++h2) {
                const float2 kf = __half22float2(kh[h2]);
                p = fmaf(qf[i][2 * h2], kf.x, p);
                p = fmaf(qf[i][2 * h2 + 1], kf.y, p);
            }
            part[i] = p;
        }
        #pragma unroll
        for (int off = 4; off >= 1; off >>= 1) {
            part[0] += __shfl_xor_sync(0xffffffffu, part[0], off);
            part[1] += __shfl_xor_sync(0xffffffffu, part[1], off);
        }
        if ((lane & 7) == 0) {
            sl[(0 * 4 + (lane >> 3)) * 33 + j] = part[0];
            sl[(1 * 4 + (lane >> 3)) * 33 + j] = part[1];
        }
    }
    __syncwarp();

    {
        const int h  = lane >> 2;
        const int j0 = lane & 3;
        float vals[8];
        #pragma unroll
        for (int t = 0; t < 8; ++t) {
            const int j = j0 + 4 * t;
            vals[t] = sl[h * 33 + j] * SCALE + weights[(size_t)bq * KNN + j];
        }
        float m = vals[0];
        #pragma unroll
        for (int t = 1; t < 8; ++t) m = fmaxf(m, vals[t]);
        m = fmaxf(m, __shfl_xor_sync(0xffffffffu, m, 1));
        m = fmaxf(m, __shfl_xor_sync(0xffffffffu, m, 2));
        float s = 0.f;
        #pragma unroll
        for (int t = 0; t < 8; ++t) { vals[t] = __expf(vals[t] - m); s += vals[t]; }
        s += __shfl_xor_sync(0xffffffffu, s, 1);
        s += __shfl_xor_sync(0xffffffffu, s, 2);
        const float inv = 1.f / s;
        #pragma unroll
        for (int t = 0; t < 8; ++t) sl[h * 33 + j0 + 4 * t] = vals[t] * inv;
    }
    __syncwarp();

    float acc[2][8];
    #pragma unroll
    for (int i = 0; i < 2; ++i)
        #pragma unroll
        for (int d = 0; d < 8; ++d) acc[i][d] = 0.f;

    const int hsub = lane >> 3;
    #pragma unroll 4
    for (int j = 0; j < KNN; ++j) {
        const int ij = __shfl_sync(0xffffffffu, idxl, j);
        const uint4* vrow = reinterpret_cast<const uint4*>(vb + (size_t)ij * CC);
        #pragma unroll
        for (int i = 0; i < 2; ++i) {
            const float pj = sl[(i * 4 + hsub) * 33 + j];
            const uint4 vv = vrow[i * 32 + lane];
            const __half2* vh = reinterpret_cast<const __half2*>(&vv);
            #pragma unroll
            for (int h2 = 0; h2 < 4; ++h2) {
                const float2 vf = __half22float2(vh[h2]);
                acc[i][2 * h2]     = fmaf(pj, vf.x, acc[i][2 * h2]);
                acc[i][2 * h2 + 1] = fmaf(pj, vf.y, acc[i][2 * h2 + 1]);
            }
        }
    }

    #pragma unroll
    for (int i = 0; i < 2; ++i) {
        const size_t d = (size_t)bq * CC + i * 256 + lane * 8;
        uint32_t hw[4], lw[4];
        #pragma unroll
        for (int p = 0; p < 4; ++p) {
            float x0 = acc[i][2 * p], x1 = acc[i][2 * p + 1];
            __half h0 = __float2half_rn(x0);
            __half h1 = __float2half_rn(x1);
            __half l0 = __float2half_rn(x0 - __half2float(h0));
            __half l1 = __float2half_rn(x1 - __half2float(h1));
            hw[p] = pack2h(h0, h1);
            lw[p] = pack2h(l0, l1);
        }
        *reinterpret_cast<uint4*>(ohi + d) = make_uint4(hw[0], hw[1], hw[2], hw[3]);
        *reinterpret_cast<uint4*>(olo + d) = make_uint4(lw[0], lw[1], lw[2], lw[3]);
    }
}

// ---------------- launch ----------------------------------------------------
extern "C" void kernel_launch(void* const* d_in, const int* in_sizes, int n_in,
                              void* d_out, int out_size)
{
    const float* src = (const float*)d_in[0];
    const float* tgt = (const float*)d_in[1];
    const int*   idx = (const int*)d_in[2];
    const float* wts = (const float*)d_in[3];
    const float* Wq  = (const float*)d_in[4];
    const float* bq  = (const float*)d_in[5];
    const float* Wk  = (const float*)d_in[6];
    const float* bk  = (const float*)d_in[7];
    const float* Wv  = (const float*)d_in[8];
    const float* bv  = (const float*)d_in[9];
    const float* Wo  = (const float*)d_in[10];
    const float* bo  = (const float*)d_in[11];
    float*       out = (float*)d_out;

    void *pq, *pkh, *pvh, *pshi, *pslo, *pthi, *ptlo, *pohi, *polo, *pwt;
    cudaGetSymbolAddress(&pq, g_q);
    cudaGetSymbolAddress(&pkh, g_kh);
    cudaGetSymbolAddress(&pvh, g_vh);
    cudaGetSymbolAddress(&pshi, g_Shi);
    cudaGetSymbolAddress(&pslo, g_Slo);
    cudaGetSymbolAddress(&pthi, g_Thi);
    cudaGetSymbolAddress(&ptlo, g_Tlo);
    cudaGetSymbolAddress(&pohi, g_Ohi);
    cudaGetSymbolAddress(&polo, g_Olo);
    cudaGetSymbolAddress(&pwt, g_Wt);
    float*  gq  = (float*)pq;
    __half* gkh = (__half*)pkh;
    __half* gvh = (__half*)pvh;
    __half* shi = (__half*)pshi;
    __half* slo = (__half*)pslo;
    __half* thi = (__half*)pthi;
    __half* tlo = (__half*)ptlo;
    __half* ohi = (__half*)pohi;
    __half* olo = (__half*)polo;
    __half* wt  = (__half*)pwt;

    static bool attr_set = false;
    if (!attr_set) {
        cudaFuncSetAttribute(mma_gemm_bias<float>,
                             cudaFuncAttributeMaxDynamicSharedMemorySize, SM_TOT);
        cudaFuncSetAttribute(mma_gemm_bias<__half>,
                             cudaFuncAttributeMaxDynamicSharedMemorySize, SM_TOT);
        attr_set = true;
    }

    const size_t WS = (size_t)CC * CC;

    dim3 tgrid(CC / 32, CC / 32, 4), tblk(32, 8);
    transpose_half_all<<<tgrid, tblk>>>(Wq, Wk, Wv, Wo, wt);

    const int nsplit = MROWS * CC / 4 / 256;
    split2_kernel<<<2 * nsplit, 256>>>(src, tgt, shi, slo, thi, tlo);

    dim3 ggrid(CC / 256, MROWS / 128);   // (2, 64) = 128 CTAs
    mma_gemm_bias<float><<<ggrid, 512, SM_TOT>>>(shi, slo, wt + 0 * WS, bq, gq);
    mma_gemm_bias<__half><<<ggrid, 512, SM_TOT>>>(thi, tlo, wt + 1 * WS, bk, gkh);
    mma_gemm_bias<__half><<<ggrid, 512, SM_TOT>>>(thi, tlo, wt + 2 * WS, bv, gvh);

    attn_kernel<<<BB * HW / 8, 256>>>(gq, gkh, gvh, idx, wts, ohi, olo);

    mma_gemm_bias<float><<<ggrid, 512, SM_TOT>>>(ohi, olo, wt + 3 * WS, bo, out);
}

// round 10
// speedup vs baseline: 1.3551x; 1.0818x over previous
#include <cuda_runtime.h>
#include <cuda_bf16.h>
#include <cuda_fp16.h>
#include <cstdint>

// Problem constants
#define BB    2
#define HW    4096
#define NTGT  4096
#define CC    512
#define HH    8
#define KNN   32
#define DH    64
#define MROWS (BB * HW)      // 8192
#define SCALE 0.125f

// ---------------- scratch (device globals: allocation-free) ----------------
__device__ float  g_q[(size_t)MROWS * CC];
__device__ __half g_kh[(size_t)MROWS * CC];
__device__ __half g_vh[(size_t)MROWS * CC];
__device__ __half g_Shi[(size_t)MROWS * CC];
__device__ __half g_Slo[(size_t)MROWS * CC];
__device__ __half g_Thi[(size_t)MROWS * CC];
__device__ __half g_Tlo[(size_t)MROWS * CC];
__device__ __half g_Ohi[(size_t)MROWS * CC];
__device__ __half g_Olo[(size_t)MROWS * CC];
__device__ __half g_Wt[4][CC * CC];            // [N][K] fp16

// ---------------- helpers ----------------------------------------------------
__device__ __forceinline__ uint32_t smem_to_u32(const void* p) {
    uint32_t a;
    asm("{ .reg .u64 t; cvta.to.shared.u64 t, %1; cvt.u32.u64 %0, t; }"
        : "=r"(a) : "l"(p));
    return a;
}
__device__ __forceinline__ void cp16(uint32_t dst, const void* src) {
    asm volatile("cp.async.cg.shared.global [%0], [%1], 16;" :: "r"(dst), "l"(src));
}
#define CP_COMMIT() asm volatile("cp.async.commit_group;" ::: "memory")
#define CP_WAIT(n)  asm volatile("cp.async.wait_group %0;" :: "n"(n) : "memory")

__device__ __forceinline__ uint32_t pack2h(__half a, __half b) {
    __half2 t = __halves2half2(a, b);
    return *reinterpret_cast<uint32_t*>(&t);
}

#define MMA_F16(d, a0, a1, a2, a3, b0, b1) \
    asm volatile( \
        "mma.sync.aligned.m16n8k16.row.col.f32.f16.f16.f32 " \
        "{%0,%1,%2,%3}, {%4,%5,%6,%7}, {%8,%9}, {%0,%1,%2,%3};" \
        : "+f"((d)[0]), "+f"((d)[1]), "+f"((d)[2]), "+f"((d)[3]) \
        : "r"(a0), "r"(a1), "r"(a2), "r"(a3), "r"(b0), "r"(b1))

// ---------------- fused weight transpose -> fp16 [N][K] ---------------------
__global__ void transpose_half_all(const float* __restrict__ W0,
                                   const float* __restrict__ W1,
                                   const float* __restrict__ W2,
                                   const float* __restrict__ W3,
                                   __half* __restrict__ out)
{
    __shared__ float t[32][33];
    const int w  = blockIdx.z;
    const float* W = (w == 0) ? W0 : (w == 1) ? W1 : (w == 2) ? W2 : W3;
    const size_t wo = (size_t)w * CC * CC;
    const int kt = blockIdx.x * 32;
    const int nt = blockIdx.y * 32;
    const int tx = threadIdx.x, ty = threadIdx.y;
    #pragma unroll
    for (int i = 0; i < 4; ++i)
        t[ty + i * 8][tx] = W[(size_t)(kt + ty + i * 8) * CC + nt + tx];
    __syncthreads();
    #pragma unroll
    for (int i = 0; i < 4; ++i) {
        float x = t[tx][ty + i * 8];
        out[wo + (size_t)(nt + ty + i * 8) * CC + kt + tx] = __float2half_rn(x);
    }
}

// ---------------- fused activation split: src + tgt -> fp16 hi/lo ----------
__global__ void __launch_bounds__(256) split2_kernel(
    const float* __restrict__ S, const float* __restrict__ T,
    __half* __restrict__ shi, __half* __restrict__ slo,
    __half* __restrict__ thi, __half* __restrict__ tlo)
{
    const int half = gridDim.x >> 1;
    const bool is_t = blockIdx.x >= half;
    const float* X = is_t ? T : S;
    __half* hi = is_t ? thi : shi;
    __half* lo = is_t ? tlo : slo;
    const int i = (is_t ? blockIdx.x - half : blockIdx.x) * 256 + threadIdx.x;
    const float4 x = reinterpret_cast<const float4*>(X)[i];
    __half h0 = __float2half_rn(x.x);
    __half h1 = __float2half_rn(x.y);
    __half h2 = __float2half_rn(x.z);
    __half h3 = __float2half_rn(x.w);
    __half l0 = __float2half_rn(x.x - __half2float(h0));
    __half l1 = __float2half_rn(x.y - __half2float(h1));
    __half l2 = __float2half_rn(x.z - __half2float(h2));
    __half l3 = __float2half_rn(x.w - __half2float(h3));
    reinterpret_cast<uint2*>(hi)[i] = make_uint2(pack2h(h0, h1), pack2h(h2, h3));
    reinterpret_cast<uint2*>(lo)[i] = make_uint2(pack2h(l0, l1), pack2h(l2, l3));
}

// ---------------- fp16 2-term mma GEMM: BK=64, 2-stage ----------------------
#define ROWB 144                        // 128B data + 16B pad (ldmatrix conflict-free)
#define A_STG (128 * ROWB)              // 18432
#define B_STG (256 * ROWB)              // 36864
#define OFF_AHI 0
#define OFF_ALO (2 * A_STG)             // 36864
#define OFF_B   (4 * A_STG)             // 73728
#define SM_TOT  (OFF_B + 2 * B_STG)     // 147456

template <typename OutT>
__device__ __forceinline__ void store2(OutT* p, float a, float b);
template <> __device__ __forceinline__ void store2<float>(float* p, float a, float b) {
    *reinterpret_cast<float2*>(p) = make_float2(a, b);
}
template <> __device__ __forceinline__ void store2<__half>(__half* p, float a, float b) {
    *reinterpret_cast<__half2*>(p) = __floats2half2_rn(a, b);
}

template <typename OutT>
__global__ void __launch_bounds__(512, 1) mma_gemm_bias(
    const __half* __restrict__ Ahi, const __half* __restrict__ Alo,
    const __half* __restrict__ Wt,
    const float* __restrict__ bias, OutT* __restrict__ C)
{
    extern __shared__ char sm[];
    const uint32_t sb = smem_to_u32(sm);
    const int tid  = threadIdx.x;
    const int wid  = tid >> 5;
    const int lane = tid & 31;
    const int bm   = blockIdx.y * 128;
    const int bn   = blockIdx.x * 256;
    const int wm   = wid & 1;
    const int wn   = wid >> 1;

    const int lr = tid >> 3;            // 0..63
    const int lq = tid & 7;             // 16B chunk 0..7

    float acc[4][4][4];
    #pragma unroll
    for (int a = 0; a < 4; ++a)
        #pragma unroll
        for (int b = 0; b < 4; ++b)
            #pragma unroll
            for (int c = 0; c < 4; ++c) acc[a][b][c] = 0.f;

    auto load_stage = [&](int s, int kt) {
        const int kb = kt * 64;
        #pragma unroll
        for (int i = 0; i < 2; ++i) {             // A: 128 rows x 8 chunks
            const int row = i * 64 + lr;
            const uint32_t so = (uint32_t)(row * ROWB + lq * 16 + s * A_STG);
            const size_t  ga = (size_t)(bm + row) * CC + kb + lq * 8;
            cp16(sb + OFF_AHI + so, Ahi + ga);
            cp16(sb + OFF_ALO + so, Alo + ga);
        }
        #pragma unroll
        for (int i = 0; i < 4; ++i) {             // B: 256 rows x 8 chunks
            const int row = i * 64 + lr;
            const uint32_t so = (uint32_t)(row * ROWB + lq * 16 + s * B_STG);
            const size_t  gb = (size_t)(bn + row) * CC + kb + lq * 8;
            cp16(sb + OFF_B + so, Wt + gb);
        }
    };

    load_stage(0, 0);
    CP_COMMIT();

    const int sub16 = lane & 15;
    const int ahalf = lane >> 4;
    const int bn8   = lane & 7;
    const int bk16  = (lane >> 3) & 1;

    #pragma unroll 1
    for (int kt = 0; kt < 8; ++kt) {
        const int s = kt & 1;
        CP_WAIT(0);
        __syncthreads();
        if (kt + 1 < 8) {
            load_stage(s ^ 1, kt + 1);
            CP_COMMIT();
        }

        const uint32_t aBase = sb + (uint32_t)(s * A_STG);
        const uint32_t bBase = sb + (uint32_t)(s * B_STG);

        #pragma unroll
        for (int s2 = 0; s2 < 4; ++s2) {
            const int kbyte = s2 * 32;

            uint32_t bh[4][2];
            #pragma unroll
            for (int nf = 0; nf < 4; ++nf) {
                const uint32_t brow = (uint32_t)(wn * 32 + nf * 8 + bn8);
                const uint32_t ba = bBase + brow * ROWB + kbyte + bk16 * 16;
                asm volatile(
                    "ldmatrix.sync.aligned.m8n8.x2.shared.b16 {%0,%1}, [%2];"
                    : "=r"(bh[nf][0]), "=r"(bh[nf][1]) : "r"(ba + OFF_B));
            }
            uint32_t ah[4][4], al[4][4];
            #pragma unroll
            for (int mf = 0; mf < 4; ++mf) {
                const uint32_t arow = (uint32_t)(wm * 64 + mf * 16 + sub16);
                const uint32_t aa = aBase + arow * ROWB + kbyte + ahalf * 16;
                asm volatile(
                    "ldmatrix.sync.aligned.m8n8.x4.shared.b16 {%0,%1,%2,%3}, [%4];"
                    : "=r"(ah[mf][0]), "=r"(ah[mf][1]), "=r"(ah[mf][2]), "=r"(ah[mf][3])
                    : "r"(aa + OFF_AHI));
                asm volatile(
                    "ldmatrix.sync.aligned.m8n8.x4.shared.b16 {%0,%1,%2,%3}, [%4];"
                    : "=r"(al[mf][0]), "=r"(al[mf][1]), "=r"(al[mf][2]), "=r"(al[mf][3])
                    : "r"(aa + OFF_ALO));
            }

            #pragma unroll
            for (int mf = 0; mf < 4; ++mf)
                #pragma unroll
                for (int nf = 0; nf < 4; ++nf)
                    MMA_F16(acc[mf][nf], ah[mf][0], ah[mf][1], ah[mf][2], ah[mf][3],
                            bh[nf][0], bh[nf][1]);
            #pragma unroll
            for (int mf = 0; mf < 4; ++mf)
                #pragma unroll
                for (int nf = 0; nf < 4; ++nf)
                    MMA_F16(acc[mf][nf], al[mf][0], al[mf][1], al[mf][2], al[mf][3],
                            bh[nf][0], bh[nf][1]);
        }
    }

    const int g = lane >> 2;
    const int t = lane & 3;
    #pragma unroll
    for (int mf = 0; mf < 4; ++mf) {
        const int row = bm + wm * 64 + mf * 16 + g;
        #pragma unroll
        for (int nf = 0; nf < 4; ++nf) {
            const int col = bn + wn * 32 + nf * 8 + 2 * t;
            const float b0 = __ldg(bias + col);
            const float b1 = __ldg(bias + col + 1);
            float* d = acc[mf][nf];
            store2<OutT>(C + (size_t)row * CC + col, d[0] + b0, d[1] + b1);
            store2<OutT>(C + (size_t)(row + 8) * CC + col, d[2] + b0, d[3] + b1);
        }
    }
}

// ---------------- gather attention: fp16 K/V, one warp per (b,q) ------------
__global__ void __launch_bounds__(256) attn_kernel(
    const float* __restrict__ q, const __half* __restrict__ k,
    const __half* __restrict__ v, const int* __restrict__ indices,
    const float* __restrict__ weights,
    __half* __restrict__ ohi, __half* __restrict__ olo)
{
    __shared__ float slog[8 * 8 * 33];
    const int wid  = threadIdx.x >> 5;
    const int lane = threadIdx.x & 31;
    const int bq   = blockIdx.x * 8 + wid;
    const int b    = bq >> 12;
    float* sl = slog + wid * (8 * 33);

    const __half* kb = k + (size_t)b * NTGT * CC;
    const __half* vb = v + (size_t)b * NTGT * CC;

    const int idxl = indices[(size_t)bq * KNN + lane];

    float qf[2][8];
    {
        const float4* qrow = reinterpret_cast<const float4*>(q + (size_t)bq * CC);
        #pragma unroll
        for (int i = 0; i < 2; ++i) {
            float4 a = qrow[i * 64 + lane * 2];
            float4 c = qrow[i * 64 + lane * 2 + 1];
            qf[i][0] = a.x; qf[i][1] = a.y; qf[i][2] = a.z; qf[i][3] = a.w;
            qf[i][4] = c.x; qf[i][5] = c.y; qf[i][6] = c.z; qf[i][7] = c.w;
        }
    }

    #pragma unroll 4
    for (int j = 0; j < KNN; ++j) {
        const int ij = __shfl_sync(0xffffffffu, idxl, j);
        const uint4* krow = reinterpret_cast<const uint4*>(kb + (size_t)ij * CC);
        float part[2];
        #pragma unroll
        for (int i = 0; i < 2; ++i) {
            const uint4 kk = krow[i * 32 + lane];
            const __half2* kh = reinterpret_cast<const __half2*>(&kk);
            float p = 0.f;
            #pragma unroll
            for (int h2 = 0; h2 < 4; ++h2) {
                const float2 kf = __half22float2(kh[h2]);
                p = fmaf(qf[i][2 * h2], kf.x, p);
                p = fmaf(qf[i][2 * h2 + 1], kf.y, p);
            }
            part[i] = p;
        }
        #pragma unroll
        for (int off = 4; off >= 1; off >>= 1) {
            part[0] += __shfl_xor_sync(0xffffffffu, part[0], off);
            part[1] += __shfl_xor_sync(0xffffffffu, part[1], off);
        }
        if ((lane & 7) == 0) {
            sl[(0 * 4 + (lane >> 3)) * 33 + j] = part[0];
            sl[(1 * 4 + (lane >> 3)) * 33 + j] = part[1];
        }
    }
    __syncwarp();

    {
        const int h  = lane >> 2;
        const int j0 = lane & 3;
        float vals[8];
        #pragma unroll
        for (int t = 0; t < 8; ++t) {
            const int j = j0 + 4 * t;
            vals[t] = sl[h * 33 + j] * SCALE + weights[(size_t)bq * KNN + j];
        }
        float m = vals[0];
        #pragma unroll
        for (int t = 1; t < 8; ++t) m = fmaxf(m, vals[t]);
        m = fmaxf(m, __shfl_xor_sync(0xffffffffu, m, 1));
        m = fmaxf(m, __shfl_xor_sync(0xffffffffu, m, 2));
        float s = 0.f;
        #pragma unroll
        for (int t = 0; t < 8; ++t) { vals[t] = __expf(vals[t] - m); s += vals[t]; }
        s += __shfl_xor_sync(0xffffffffu, s, 1);
        s += __shfl_xor_sync(0xffffffffu, s, 2);
        const float inv = 1.f / s;
        #pragma unroll
        for (int t = 0; t < 8; ++t) sl[h * 33 + j0 + 4 * t] = vals[t] * inv;
    }
    __syncwarp();

    float acc[2][8];
    #pragma unroll
    for (int i = 0; i < 2; ++i)
        #pragma unroll
        for (int d = 0; d < 8; ++d) acc[i][d] = 0.f;

    const int hsub = lane >> 3;
    #pragma unroll 4
    for (int j = 0; j < KNN; ++j) {
        const int ij = __shfl_sync(0xffffffffu, idxl, j);
        const uint4* vrow = reinterpret_cast<const uint4*>(vb + (size_t)ij * CC);
        #pragma unroll
        for (int i = 0; i < 2; ++i) {
            const float pj = sl[(i * 4 + hsub) * 33 + j];
            const uint4 vv = vrow[i * 32 + lane];
            const __half2* vh = reinterpret_cast<const __half2*>(&vv);
            #pragma unroll
            for (int h2 = 0; h2 < 4; ++h2) {
                const float2 vf = __half22float2(vh[h2]);
                acc[i][2 * h2]     = fmaf(pj, vf.x, acc[i][2 * h2]);
                acc[i][2 * h2 + 1] = fmaf(pj, vf.y, acc[i][2 * h2 + 1]);
            }
        }
    }

    #pragma unroll
    for (int i = 0; i < 2; ++i) {
        const size_t d = (size_t)bq * CC + i * 256 + lane * 8;
        uint32_t hw[4], lw[4];
        #pragma unroll
        for (int p = 0; p < 4; ++p) {
            float x0 = acc[i][2 * p], x1 = acc[i][2 * p + 1];
            __half h0 = __float2half_rn(x0);
            __half h1 = __float2half_rn(x1);
            __half l0 = __float2half_rn(x0 - __half2float(h0));
            __half l1 = __float2half_rn(x1 - __half2float(h1));
            hw[p] = pack2h(h0, h1);
            lw[p] = pack2h(l0, l1);
        }
        *reinterpret_cast<uint4*>(ohi + d) = make_uint4(hw[0], hw[1], hw[2], hw[3]);
        *reinterpret_cast<uint4*>(olo + d) = make_uint4(lw[0], lw[1], lw[2], lw[3]);
    }
}

// ---------------- launch ----------------------------------------------------
extern "C" void kernel_launch(void* const* d_in, const int* in_sizes, int n_in,
                              void* d_out, int out_size)
{
    const float* src = (const float*)d_in[0];
    const float* tgt = (const float*)d_in[1];
    const int*   idx = (const int*)d_in[2];
    const float* wts = (const float*)d_in[3];
    const float* Wq  = (const float*)d_in[4];
    const float* bq  = (const float*)d_in[5];
    const float* Wk  = (const float*)d_in[6];
    const float* bk  = (const float*)d_in[7];
    const float* Wv  = (const float*)d_in[8];
    const float* bv  = (const float*)d_in[9];
    const float* Wo  = (const float*)d_in[10];
    const float* bo  = (const float*)d_in[11];
    float*       out = (float*)d_out;

    void *pq, *pkh, *pvh, *pshi, *pslo, *pthi, *ptlo, *pohi, *polo, *pwt;
    cudaGetSymbolAddress(&pq, g_q);
    cudaGetSymbolAddress(&pkh, g_kh);
    cudaGetSymbolAddress(&pvh, g_vh);
    cudaGetSymbolAddress(&pshi, g_Shi);
    cudaGetSymbolAddress(&pslo, g_Slo);
    cudaGetSymbolAddress(&pthi, g_Thi);
    cudaGetSymbolAddress(&ptlo, g_Tlo);
    cudaGetSymbolAddress(&pohi, g_Ohi);
    cudaGetSymbolAddress(&polo, g_Olo);
    cudaGetSymbolAddress(&pwt, g_Wt);
    float*  gq  = (float*)pq;
    __half* gkh = (__half*)pkh;
    __half* gvh = (__half*)pvh;
    __half* shi = (__half*)pshi;
    __half* slo = (__half*)pslo;
    __half* thi = (__half*)pthi;
    __half* tlo = (__half*)ptlo;
    __half* ohi = (__half*)pohi;
    __half* olo = (__half*)polo;
    __half* wt  = (__half*)pwt;

    static bool attr_set = false;
    if (!attr_set) {
        cudaFuncSetAttribute(mma_gemm_bias<float>,
                             cudaFuncAttributeMaxDynamicSharedMemorySize, SM_TOT);
        cudaFuncSetAttribute(mma_gemm_bias<__half>,
                             cudaFuncAttributeMaxDynamicSharedMemorySize, SM_TOT);
        attr_set = true;
    }

    const size_t WS = (size_t)CC * CC;

    dim3 tgrid(CC / 32, CC / 32, 4), tblk(32, 8);
    transpose_half_all<<<tgrid, tblk>>>(Wq, Wk, Wv, Wo, wt);

    const int nsplit = MROWS * CC / 4 / 256;
    split2_kernel<<<2 * nsplit, 256>>>(src, tgt, shi, slo, thi, tlo);

    dim3 ggrid(CC / 256, MROWS / 128);   // (2, 64) = 128 CTAs
    mma_gemm_bias<float><<<ggrid, 512, SM_TOT>>>(shi, slo, wt + 0 * WS, bq, gq);
    mma_gemm_bias<__half><<<ggrid, 512, SM_TOT>>>(thi, tlo, wt + 1 * WS, bk, gkh);
    mma_gemm_bias<__half><<<ggrid, 512, SM_TOT>>>(thi, tlo, wt + 2 * WS, bv, gvh);

    attn_kernel<<<BB * HW / 8, 256>>>(gq, gkh, gvh, idx, wts, ohi, olo);

    mma_gemm_bias<float><<<ggrid, 512, SM_TOT>>>(ohi, olo, wt + 3 * WS, bo, out);
}